// round 7
// baseline (speedup 1.0000x reference)
#include <cuda_runtime.h>
#include <cuda_bf16.h>
#include <cstdint>

#define BATCH 8
#define HH 512
#define WW 512

// h stored as bf16 hi/lo, grouped 8 channels per 16B:
// g_hb[((b*8+g)*512 + y)*512 + x] : uint4 = 8 bf16 (g<4: hi oc 8g..8g+7, g>=4: lo)
__device__ uint4 g_hb[(size_t)BATCH * 8 * HH * WW];

typedef unsigned long long u64;
typedef unsigned short u16;
typedef unsigned int u32;

__device__ __forceinline__ u64 pk2(float lo, float hi) {
    u64 r; asm("mov.b64 %0, {%1, %2};" : "=l"(r) : "f"(lo), "f"(hi)); return r;
}
__device__ __forceinline__ void upk2(u64 p, float& lo, float& hi) {
    asm("mov.b64 {%0, %1}, %2;" : "=f"(lo), "=f"(hi) : "l"(p));
}
#define FMA2(acc, w, v) asm("fma.rn.f32x2 %0, %1, %2, %0;" : "+l"(acc) : "l"(w), "l"(v))

__device__ __forceinline__ u32 smem_u32(const void* p) {
    u32 a;
    asm("{ .reg .u64 t; cvta.to.shared.u64 t, %1; cvt.u32.u64 %0, t; }" : "=r"(a) : "l"(p));
    return a;
}

// ---------------------------------------------------------------------------
// Kernel 1: conv5x5 (2->32) + bias + LeakyReLU -> bf16 hi/lo split, grouped.
// ---------------------------------------------------------------------------
__global__ __launch_bounds__(256, 2) void conv1_kernel(
    const float* __restrict__ img, const float* __restrict__ ref,
    const float* __restrict__ w1, const float* __restrict__ b1)
{
    __shared__ __align__(16) float sIn[2][36 * 40];
    __shared__ __align__(16) u64 sW[800];

    const int tid = threadIdx.x;
    const int bx = blockIdx.x, by = blockIdx.y, b = blockIdx.z;
    const int gx0 = bx * 32 - 2, gy0 = by * 32 - 2;

    const float* ib = img + (size_t)b * HH * WW;
    const float* rb = ref + (size_t)b * HH * WW;

    for (int i = tid; i < 36 * 40; i += 256) {
        int yy = i / 40, xx = i - yy * 40;
        int gy = gy0 + yy, gx = gx0 + xx;
        bool ok = ((unsigned)gy < HH) && ((unsigned)gx < WW) && (xx < 36);
        sIn[0][i] = ok ? ib[gy * WW + gx] : 0.f;
        sIn[1][i] = ok ? rb[gy * WW + gx] : 0.f;
    }
    for (int i = tid; i < 800; i += 256) {
        int p = i & 3, t = i >> 2;
        int k = t % 25, cw = t / 25;
        int q = cw >> 1, ci = cw & 1;
        int oc = q * 8 + 2 * p;
        float wlo = w1[(oc * 2 + ci) * 25 + k];
        float whi = w1[((oc + 1) * 2 + ci) * 25 + k];
        sW[i] = pk2(wlo, whi);
    }
    __syncthreads();

    const int lx0 = (tid & 7) * 4, ly = tid >> 3;
    const int ox = bx * 32 + lx0, oy = by * 32 + ly;

    #pragma unroll 1
    for (int q = 0; q < 4; q++) {
        u64 acc[4][4];
        #pragma unroll
        for (int p = 0; p < 4; p++)
            #pragma unroll
            for (int r = 0; r < 4; r++) acc[p][r] = 0ull;

        #pragma unroll 1
        for (int ci = 0; ci < 2; ci++) {
            const u64* wbase = &sW[(q * 2 + ci) * 100];
            const float* hbase = &sIn[ci][ly * 40 + lx0];
            #pragma unroll
            for (int dy = 0; dy < 5; dy++) {
                const float* rp = hbase + dy * 40;
                float4 a0 = *(const float4*)rp;
                float4 a1 = *(const float4*)(rp + 4);
                u64 D[8];
                D[0] = pk2(a0.x, a0.x); D[1] = pk2(a0.y, a0.y);
                D[2] = pk2(a0.z, a0.z); D[3] = pk2(a0.w, a0.w);
                D[4] = pk2(a1.x, a1.x); D[5] = pk2(a1.y, a1.y);
                D[6] = pk2(a1.z, a1.z); D[7] = pk2(a1.w, a1.w);
                #pragma unroll
                for (int dx = 0; dx < 5; dx++) {
                    const ulonglong2* wp =
                        (const ulonglong2*)(wbase + (dy * 5 + dx) * 4);
                    ulonglong2 wA = wp[0], wB = wp[1];
                    #pragma unroll
                    for (int r = 0; r < 4; r++) {
                        u64 v = D[dx + r];
                        FMA2(acc[0][r], wA.x, v);
                        FMA2(acc[1][r], wA.y, v);
                        FMA2(acc[2][r], wB.x, v);
                        FMA2(acc[3][r], wB.y, v);
                    }
                }
            }
        }

        float bs[8];
        #pragma unroll
        for (int o = 0; o < 8; o++) bs[o] = __ldg(&b1[q * 8 + o]);

        #pragma unroll
        for (int r = 0; r < 4; r++) {
            float v[8];
            #pragma unroll
            for (int p = 0; p < 4; p++) upk2(acc[p][r], v[2 * p], v[2 * p + 1]);
            u32 hw[4], lw[4];
            #pragma unroll
            for (int p = 0; p < 4; p++) {
                float a0 = v[2 * p] + bs[2 * p];
                float a1 = v[2 * p + 1] + bs[2 * p + 1];
                a0 = a0 >= 0.f ? a0 : 0.1f * a0;
                a1 = a1 >= 0.f ? a1 : 0.1f * a1;
                __nv_bfloat16 h0 = __float2bfloat16(a0);
                __nv_bfloat16 h1 = __float2bfloat16(a1);
                __nv_bfloat16 l0 = __float2bfloat16(a0 - __bfloat162float(h0));
                __nv_bfloat16 l1 = __float2bfloat16(a1 - __bfloat162float(h1));
                hw[p] = (u32)__bfloat16_as_ushort(h0) |
                        ((u32)__bfloat16_as_ushort(h1) << 16);
                lw[p] = (u32)__bfloat16_as_ushort(l0) |
                        ((u32)__bfloat16_as_ushort(l1) << 16);
            }
            size_t pix = (size_t)oy * WW + ox + r;
            g_hb[((size_t)(b * 8 + q) * HH * WW) + pix] =
                make_uint4(hw[0], hw[1], hw[2], hw[3]);
            g_hb[((size_t)(b * 8 + 4 + q) * HH * WW) + pix] =
                make_uint4(lw[0], lw[1], lw[2], lw[3]);
        }
    }
}

// ---------------------------------------------------------------------------
// Kernel 2: mma.sync bf16 implicit-GEMM conv2 + fused dynamic-filter apply.
// 256 threads (8 warps). CTA: 128 px x 32 rows. Warp: 16 px x 16 j.
// ---------------------------------------------------------------------------
#define A_PITCH 144                       // bytes per pixel row (128 data + 16 pad)
#define A_SLOT (132 * A_PITCH)            // 19008
#define A_OFF 0
#define B_OFF (5 * A_SLOT)                // 95040
#define B_SIZE (25 * 4 * 32 * 16)         // 51200
#define IMG_OFF (B_OFF + B_SIZE)          // 146240
#define IMG_PITCH 136
#define SMEM_TOTAL (IMG_OFF + 3 * IMG_PITCH * 4)

__device__ __forceinline__ void ldmatrix4(u32& a0, u32& a1, u32& a2, u32& a3, u32 addr) {
    asm volatile("ldmatrix.sync.aligned.m8n8.x4.shared.b16 {%0,%1,%2,%3}, [%4];"
                 : "=r"(a0), "=r"(a1), "=r"(a2), "=r"(a3) : "r"(addr));
}
__device__ __forceinline__ void mma16816(float* c, const u32* a, u32 b0, u32 b1) {
    asm volatile(
        "mma.sync.aligned.m16n8k16.row.col.f32.bf16.bf16.f32 "
        "{%0,%1,%2,%3}, {%4,%5,%6,%7}, {%8,%9}, {%0,%1,%2,%3};"
        : "+f"(c[0]), "+f"(c[1]), "+f"(c[2]), "+f"(c[3])
        : "r"(a[0]), "r"(a[1]), "r"(a[2]), "r"(a[3]), "r"(b0), "r"(b1));
}

__global__ __launch_bounds__(256, 1) void conv2_mma_kernel(
    const float* __restrict__ w2, const float* __restrict__ b2,
    const float* __restrict__ img, float* __restrict__ out)
{
    extern __shared__ __align__(16) char smem[];
    const u32 sbase = smem_u32(smem);
    const int tid = threadIdx.x;
    const int wid = tid >> 5, lane = tid & 31;
    const int x0 = blockIdx.x * 128;
    const int y0 = blockIdx.y * 32;
    const int b = blockIdx.z;

    // ---- pack B fragments: [tap][bsel][thread][4 regs] ----
    // bsel 0: whi ch0-15, 1: whi ch16-31, 2: wlo ch0-15, 3: wlo ch16-31
    for (int i = tid; i < 25 * 4 * 32; i += 256) {
        int t = i & 31, bs = (i >> 5) & 3, tap = i >> 7;
        int q = t & 3, g = t >> 2;
        u32 regs[4];
        #pragma unroll
        for (int rr = 0; rr < 4; rr++) {
            int ntile = rr >> 1;
            int kb = (rr & 1) * 8;
            int n = g + ntile * 8;
            int k0 = 2 * q + kb;
            u16 v0 = 0, v1 = 0;
            if (n < 9) {
                int ch0 = (bs & 1) * 16 + k0;
                float w0 = __ldg(&w2[(n * 32 + ch0) * 25 + tap]);
                float w1 = __ldg(&w2[(n * 32 + ch0 + 1) * 25 + tap]);
                __nv_bfloat16 h0 = __float2bfloat16(w0);
                __nv_bfloat16 h1 = __float2bfloat16(w1);
                if (bs < 2) {
                    v0 = __bfloat16_as_ushort(h0);
                    v1 = __bfloat16_as_ushort(h1);
                } else {
                    v0 = __bfloat16_as_ushort(
                        __float2bfloat16(w0 - __bfloat162float(h0)));
                    v1 = __bfloat16_as_ushort(
                        __float2bfloat16(w1 - __bfloat162float(h1)));
                }
            }
            regs[rr] = (u32)v0 | ((u32)v1 << 16);
        }
        *(uint4*)(smem + B_OFF + i * 16) = make_uint4(regs[0], regs[1], regs[2], regs[3]);
    }

    // per-thread bias (zero-padded beyond j=8)
    const int q = lane & 3, g = lane >> 2;
    float bjv[4];
    #pragma unroll
    for (int rr = 0; rr < 4; rr++) {
        int j = 2 * q + (rr & 1) + (rr >> 1) * 8;
        bjv[rr] = (j < 9) ? __ldg(&b2[j]) : 0.f;
    }

    const float* ib = img + (size_t)b * HH * WW;

    auto fillA = [&](int slot, int yh) {
        char* base = smem + A_OFF + slot * A_SLOT;
        if ((unsigned)yh >= HH) {
            for (int i = tid; i < 1056; i += 256) {
                int px = i >> 3, gg = i & 7;
                *(uint4*)(base + px * A_PITCH + gg * 16) = make_uint4(0, 0, 0, 0);
            }
        } else {
            for (int i = tid; i < 1056; i += 256) {
                int px = i >> 3, gg = i & 7;
                int x = x0 - 2 + px;
                uint4 v = make_uint4(0, 0, 0, 0);
                if ((unsigned)x < WW)
                    v = g_hb[((size_t)(b * 8 + gg) * HH + yh) * WW + x];
                *(uint4*)(base + px * A_PITCH + gg * 16) = v;
            }
        }
    };
    auto fillImg = [&](int slot, int yi) {
        float* basep = (float*)(smem + IMG_OFF) + slot * IMG_PITCH;
        for (int i = tid; i < 132; i += 256) {
            int x = x0 - 2 + i;
            basep[i] = (((unsigned)yi < HH) && ((unsigned)x < WW))
                           ? ib[yi * WW + x] : 0.f;
        }
    };

    for (int d = -2; d <= 1; d++) fillA(((y0 + d) % 5 + 5) % 5, y0 + d);
    fillImg(((y0 - 1) % 3 + 3) % 3, y0 - 1);
    fillImg(y0 % 3, y0);

    // per-thread ldmatrix address component
    const u32 PW = (u32)((wid * 16 + (lane & 15)) * A_PITCH + (lane >> 4) * 16);
    const u32 aBase = sbase + A_OFF;
    const u32 bBase = sbase + B_OFF;

    static const u32 koffs[6] = {0, 32, 64, 96, 0, 32};
    static const int bsels[6] = {0, 1, 0, 1, 2, 3};

    #pragma unroll 1
    for (int y = y0; y < y0 + 32; y++) {
        fillA((y + 2) % 5, y + 2);
        fillImg((y + 1) % 3, y + 1);
        __syncthreads();

        float c0[4] = {0.f, 0.f, 0.f, 0.f};   // n-tile 0 (j 0-7)
        float c1[4] = {0.f, 0.f, 0.f, 0.f};   // n-tile 1 (j 8-15)

        #pragma unroll 1
        for (int dy = 0; dy < 5; dy++) {
            int slot = (y + dy - 2 + 5) % 5;
            u32 rowBase = aBase + (u32)slot * A_SLOT + PW;
            #pragma unroll
            for (int dx = 0; dx < 5; dx++) {
                u32 ab = rowBase + (u32)dx * A_PITCH;
                int tap = dy * 5 + dx;
                #pragma unroll
                for (int cch = 0; cch < 6; cch++) {
                    u32 a[4];
                    ldmatrix4(a[0], a[1], a[2], a[3], ab + koffs[cch]);
                    uint4 bf = *(const uint4*)(smem + B_OFF +
                        (((tap * 4 + bsels[cch]) * 32 + lane) << 4));
                    mma16816(c0, a, bf.x, bf.y);
                    mma16816(c1, a, bf.z, bf.w);
                }
            }
        }

        // epilogue: bias + dynamic 3x3 apply + quad reduce
        const float* imgb = (const float*)(smem + IMG_OFF);
        int px0 = wid * 16 + g;          // rows g and g+8 of warp tile
        float o0 = 0.f, o1 = 0.f;
        #pragma unroll
        for (int rr = 0; rr < 4; rr++) {
            int j = 2 * q + (rr & 1) + (rr >> 1) * 8;
            int jy = j / 3, jx = j - 3 * jy;         // j>=9: harmless (f+0)*x
            if (j < 9) {
                int slot = (y + jy - 1 + 3) % 3;
                const float* irow = imgb + slot * IMG_PITCH;
                float f0 = ((rr >> 1) ? c1[rr & 1] : c0[rr & 1]) + bjv[rr];
                float f1 = ((rr >> 1) ? c1[(rr & 1) + 2] : c0[(rr & 1) + 2]) + bjv[rr];
                o0 += f0 * irow[px0 + 1 + jx];
                o1 += f1 * irow[px0 + 8 + 1 + jx];
            }
        }
        // quad reduce (lanes differing in bits 0-1 share pixels)
        o0 += __shfl_xor_sync(0xffffffffu, o0, 1);
        o0 += __shfl_xor_sync(0xffffffffu, o0, 2);
        o1 += __shfl_xor_sync(0xffffffffu, o1, 1);
        o1 += __shfl_xor_sync(0xffffffffu, o1, 2);
        if (q == 0) {
            float* orow = out + ((size_t)b * HH + y) * WW + x0;
            orow[px0] = o0;
            orow[px0 + 8] = o1;
        }
        __syncthreads();
    }
}

extern "C" void kernel_launch(void* const* d_in, const int* in_sizes, int n_in,
                              void* d_out, int out_size) {
    const float* image = (const float*)d_in[0];
    const float* refer = (const float*)d_in[1];
    const float* w1    = (const float*)d_in[2];
    const float* b1    = (const float*)d_in[3];
    const float* w2    = (const float*)d_in[4];
    const float* b2    = (const float*)d_in[5];
    float* out = (float*)d_out;

    cudaFuncSetAttribute(conv2_mma_kernel,
                         cudaFuncAttributeMaxDynamicSharedMemorySize, SMEM_TOTAL);

    dim3 grid1(WW / 32, HH / 32, BATCH);
    conv1_kernel<<<grid1, 256>>>(image, refer, w1, b1);

    dim3 grid2(WW / 128, HH / 32, BATCH);
    conv2_mma_kernel<<<grid2, 256, SMEM_TOTAL>>>(w2, b2, image, out);
}

// round 8
// speedup vs baseline: 1.3876x; 1.3876x over previous
#include <cuda_runtime.h>
#include <cuda_bf16.h>
#include <cstdint>

#define BATCH 8
#define HH 512
#define WW 512

// h stored as bf16 hi/lo, grouped 8 channels per 16B:
// g_hb[((b*8+g)*512 + y)*512 + x] : uint4 = 8 bf16 (g<4: hi oc 8g..8g+7, g>=4: lo)
__device__ uint4 g_hb[(size_t)BATCH * 8 * HH * WW];

typedef unsigned long long u64;
typedef unsigned short u16;
typedef unsigned int u32;

__device__ __forceinline__ u64 pk2(float lo, float hi) {
    u64 r; asm("mov.b64 %0, {%1, %2};" : "=l"(r) : "f"(lo), "f"(hi)); return r;
}
__device__ __forceinline__ void upk2(u64 p, float& lo, float& hi) {
    asm("mov.b64 {%0, %1}, %2;" : "=f"(lo), "=f"(hi) : "l"(p));
}
#define FMA2(acc, w, v) asm("fma.rn.f32x2 %0, %1, %2, %0;" : "+l"(acc) : "l"(w), "l"(v))

__device__ __forceinline__ u32 smem_u32(const void* p) {
    u32 a;
    asm("{ .reg .u64 t; cvta.to.shared.u64 t, %1; cvt.u32.u64 %0, t; }" : "=r"(a) : "l"(p));
    return a;
}

// ---------------------------------------------------------------------------
// Kernel 1: conv5x5 (2->32) + bias + LeakyReLU -> bf16 hi/lo split, grouped.
// ---------------------------------------------------------------------------
__global__ __launch_bounds__(256, 2) void conv1_kernel(
    const float* __restrict__ img, const float* __restrict__ ref,
    const float* __restrict__ w1, const float* __restrict__ b1)
{
    __shared__ __align__(16) float sIn[2][36 * 40];
    __shared__ __align__(16) u64 sW[800];

    const int tid = threadIdx.x;
    const int bx = blockIdx.x, by = blockIdx.y, b = blockIdx.z;
    const int gx0 = bx * 32 - 2, gy0 = by * 32 - 2;

    const float* ib = img + (size_t)b * HH * WW;
    const float* rb = ref + (size_t)b * HH * WW;

    for (int i = tid; i < 36 * 40; i += 256) {
        int yy = i / 40, xx = i - yy * 40;
        int gy = gy0 + yy, gx = gx0 + xx;
        bool ok = ((unsigned)gy < HH) && ((unsigned)gx < WW) && (xx < 36);
        sIn[0][i] = ok ? ib[gy * WW + gx] : 0.f;
        sIn[1][i] = ok ? rb[gy * WW + gx] : 0.f;
    }
    for (int i = tid; i < 800; i += 256) {
        int p = i & 3, t = i >> 2;
        int k = t % 25, cw = t / 25;
        int q = cw >> 1, ci = cw & 1;
        int oc = q * 8 + 2 * p;
        float wlo = w1[(oc * 2 + ci) * 25 + k];
        float whi = w1[((oc + 1) * 2 + ci) * 25 + k];
        sW[i] = pk2(wlo, whi);
    }
    __syncthreads();

    const int lx0 = (tid & 7) * 4, ly = tid >> 3;
    const int ox = bx * 32 + lx0, oy = by * 32 + ly;

    #pragma unroll 1
    for (int q = 0; q < 4; q++) {
        u64 acc[4][4];
        #pragma unroll
        for (int p = 0; p < 4; p++)
            #pragma unroll
            for (int r = 0; r < 4; r++) acc[p][r] = 0ull;

        #pragma unroll 1
        for (int ci = 0; ci < 2; ci++) {
            const u64* wbase = &sW[(q * 2 + ci) * 100];
            const float* hbase = &sIn[ci][ly * 40 + lx0];
            #pragma unroll
            for (int dy = 0; dy < 5; dy++) {
                const float* rp = hbase + dy * 40;
                float4 a0 = *(const float4*)rp;
                float4 a1 = *(const float4*)(rp + 4);
                u64 D[8];
                D[0] = pk2(a0.x, a0.x); D[1] = pk2(a0.y, a0.y);
                D[2] = pk2(a0.z, a0.z); D[3] = pk2(a0.w, a0.w);
                D[4] = pk2(a1.x, a1.x); D[5] = pk2(a1.y, a1.y);
                D[6] = pk2(a1.z, a1.z); D[7] = pk2(a1.w, a1.w);
                #pragma unroll
                for (int dx = 0; dx < 5; dx++) {
                    const ulonglong2* wp =
                        (const ulonglong2*)(wbase + (dy * 5 + dx) * 4);
                    ulonglong2 wA = wp[0], wB = wp[1];
                    #pragma unroll
                    for (int r = 0; r < 4; r++) {
                        u64 v = D[dx + r];
                        FMA2(acc[0][r], wA.x, v);
                        FMA2(acc[1][r], wA.y, v);
                        FMA2(acc[2][r], wB.x, v);
                        FMA2(acc[3][r], wB.y, v);
                    }
                }
            }
        }

        float bs[8];
        #pragma unroll
        for (int o = 0; o < 8; o++) bs[o] = __ldg(&b1[q * 8 + o]);

        #pragma unroll
        for (int r = 0; r < 4; r++) {
            float v[8];
            #pragma unroll
            for (int p = 0; p < 4; p++) upk2(acc[p][r], v[2 * p], v[2 * p + 1]);
            u32 hw[4], lw[4];
            #pragma unroll
            for (int p = 0; p < 4; p++) {
                float a0 = v[2 * p] + bs[2 * p];
                float a1 = v[2 * p + 1] + bs[2 * p + 1];
                a0 = a0 >= 0.f ? a0 : 0.1f * a0;
                a1 = a1 >= 0.f ? a1 : 0.1f * a1;
                __nv_bfloat16 h0 = __float2bfloat16(a0);
                __nv_bfloat16 h1 = __float2bfloat16(a1);
                __nv_bfloat16 l0 = __float2bfloat16(a0 - __bfloat162float(h0));
                __nv_bfloat16 l1 = __float2bfloat16(a1 - __bfloat162float(h1));
                hw[p] = (u32)__bfloat16_as_ushort(h0) |
                        ((u32)__bfloat16_as_ushort(h1) << 16);
                lw[p] = (u32)__bfloat16_as_ushort(l0) |
                        ((u32)__bfloat16_as_ushort(l1) << 16);
            }
            size_t pix = (size_t)oy * WW + ox + r;
            g_hb[((size_t)(b * 8 + q) * HH * WW) + pix] =
                make_uint4(hw[0], hw[1], hw[2], hw[3]);
            g_hb[((size_t)(b * 8 + 4 + q) * HH * WW) + pix] =
                make_uint4(lw[0], lw[1], lw[2], lw[3]);
        }
    }
}

// ---------------------------------------------------------------------------
// Kernel 2: mma.sync bf16 implicit-GEMM conv2 + fused dynamic-filter apply.
// 256 threads (8 warps). CTA: 32 px x 16 rows, all h-halo resident in smem.
// Warp: 2 y-rows x (2 x-halves) = 4 independent m16xn16 tiles.
// ---------------------------------------------------------------------------
#define A_PITCH 144
#define NPIX (20 * 36)                    // h halo: 20 rows x 36 px
#define A_OFF 0
#define A_BYTES (NPIX * A_PITCH)          // 103,680
#define B_OFF A_BYTES
#define B_SIZE (25 * 4 * 32 * 16)         // 51,200
#define IMG_OFF (B_OFF + B_SIZE)          // 154,880
#define SMEM_TOTAL (IMG_OFF + 18 * 36 * 4)

__device__ __forceinline__ void ldmatrix4(u32& a0, u32& a1, u32& a2, u32& a3, u32 addr) {
    asm volatile("ldmatrix.sync.aligned.m8n8.x4.shared.b16 {%0,%1,%2,%3}, [%4];"
                 : "=r"(a0), "=r"(a1), "=r"(a2), "=r"(a3) : "r"(addr));
}
__device__ __forceinline__ void mma16816(float* c, const u32* a, u32 b0, u32 b1) {
    asm volatile(
        "mma.sync.aligned.m16n8k16.row.col.f32.bf16.bf16.f32 "
        "{%0,%1,%2,%3}, {%4,%5,%6,%7}, {%8,%9}, {%0,%1,%2,%3};"
        : "+f"(c[0]), "+f"(c[1]), "+f"(c[2]), "+f"(c[3])
        : "r"(a[0]), "r"(a[1]), "r"(a[2]), "r"(a[3]), "r"(b0), "r"(b1));
}

__global__ __launch_bounds__(256, 1) void conv2_mma_kernel(
    const float* __restrict__ w2, const float* __restrict__ b2,
    const float* __restrict__ img, float* __restrict__ out)
{
    extern __shared__ __align__(16) char smem[];
    const u32 sbase = smem_u32(smem);
    const int tid = threadIdx.x;
    const int wid = tid >> 5, lane = tid & 31;
    const int x0 = blockIdx.x * 32;
    const int y0 = blockIdx.y * 16;
    const int b = blockIdx.z;

    // ---- pack B fragments: [tap][bsel][thread] : uint4 ----
    for (int i = tid; i < 25 * 4 * 32; i += 256) {
        int t = i & 31, bs = (i >> 5) & 3, tap = i >> 7;
        int tq = t & 3, tg = t >> 2;
        u32 regs[4];
        #pragma unroll
        for (int rr = 0; rr < 4; rr++) {
            int n = tg + (rr >> 1) * 8;
            int k0 = 2 * tq + (rr & 1) * 8;
            u16 v0 = 0, v1 = 0;
            if (n < 9) {
                int ch0 = (bs & 1) * 16 + k0;
                float w0 = __ldg(&w2[(n * 32 + ch0) * 25 + tap]);
                float w1 = __ldg(&w2[(n * 32 + ch0 + 1) * 25 + tap]);
                __nv_bfloat16 h0 = __float2bfloat16(w0);
                __nv_bfloat16 h1 = __float2bfloat16(w1);
                if (bs < 2) {
                    v0 = __bfloat16_as_ushort(h0);
                    v1 = __bfloat16_as_ushort(h1);
                } else {
                    v0 = __bfloat16_as_ushort(
                        __float2bfloat16(w0 - __bfloat162float(h0)));
                    v1 = __bfloat16_as_ushort(
                        __float2bfloat16(w1 - __bfloat162float(h1)));
                }
            }
            regs[rr] = (u32)v0 | ((u32)v1 << 16);
        }
        *(uint4*)(smem + B_OFF + i * 16) = make_uint4(regs[0], regs[1], regs[2], regs[3]);
    }

    const int q = lane & 3, g = lane >> 2;
    float bjv[4];
    #pragma unroll
    for (int rr = 0; rr < 4; rr++) {
        int j = 2 * q + (rr & 1) + (rr >> 1) * 8;
        bjv[rr] = (j < 9) ? __ldg(&b2[j]) : 0.f;
    }

    const float* ib = img + (size_t)b * HH * WW;

    // ---- fill A halo: h rows y0-2 .. y0+17, px x0-2 .. x0+33 ----
    for (int i = tid; i < NPIX * 8; i += 256) {
        int gg = i / NPIX, pix = i - gg * NPIX;
        int yy = pix / 36, xx = pix - yy * 36;
        int gy = y0 - 2 + yy, gx = x0 - 2 + xx;
        uint4 v = make_uint4(0, 0, 0, 0);
        if (((unsigned)gy < HH) && ((unsigned)gx < WW))
            v = g_hb[((size_t)(b * 8 + gg) * HH + gy) * WW + gx];
        *(uint4*)(smem + A_OFF + pix * A_PITCH + gg * 16) = v;
    }
    // ---- fill img tile: rows y0-1 .. y0+16, px x0-1 .. x0+34 ----
    for (int i = tid; i < 18 * 36; i += 256) {
        int yy = i / 36, xx = i - yy * 36;
        int gy = y0 - 1 + yy, gx = x0 - 1 + xx;
        ((float*)(smem + IMG_OFF))[i] =
            (((unsigned)gy < HH) && ((unsigned)gx < WW)) ? ib[gy * WW + gx] : 0.f;
    }
    __syncthreads();

    // per-tile ldmatrix lane addresses (tile t: row ry=2*wid+(t>>1), xhalf=t&1)
    u32 tAddr[4];
    #pragma unroll
    for (int t = 0; t < 4; t++) {
        int ry = 2 * wid + (t >> 1);
        int pix = ry * 36 + (t & 1) * 16 + (lane & 15);
        tAddr[t] = sbase + A_OFF + (u32)(pix * A_PITCH) + (u32)((lane >> 4) * 16);
    }

    float c[4][2][4];
    #pragma unroll
    for (int t = 0; t < 4; t++)
        #pragma unroll
        for (int n = 0; n < 2; n++)
            #pragma unroll
            for (int r = 0; r < 4; r++) c[t][n][r] = 0.f;

    const u32 koffs[6] = {0, 32, 64, 96, 0, 32};
    const int bsels[6] = {0, 1, 0, 1, 2, 3};

    #pragma unroll 1
    for (int dy = 0; dy < 5; dy++) {
        u32 dyOff = (u32)(dy * 36 * A_PITCH);
        #pragma unroll
        for (int dx = 0; dx < 5; dx++) {
            u32 tapOff = dyOff + (u32)(dx * A_PITCH);
            int tap = dy * 5 + dx;
            #pragma unroll
            for (int cch = 0; cch < 6; cch++) {
                uint4 bf = *(const uint4*)(smem + B_OFF +
                    (((tap * 4 + bsels[cch]) * 32 + lane) << 4));
                u32 off = tapOff + koffs[cch];
                #pragma unroll
                for (int t = 0; t < 4; t++) {
                    u32 a[4];
                    ldmatrix4(a[0], a[1], a[2], a[3], tAddr[t] + off);
                    mma16816(c[t][0], a, bf.x, bf.y);
                    mma16816(c[t][1], a, bf.z, bf.w);
                }
            }
        }
    }

    // ---- epilogue: bias + dynamic 3x3 apply + quad reduce + store ----
    const float* imgb = (const float*)(smem + IMG_OFF);
    #pragma unroll
    for (int t = 0; t < 4; t++) {
        int ry = 2 * wid + (t >> 1);
        int pxb = (t & 1) * 16 + g;
        float o0 = 0.f, o1 = 0.f;
        #pragma unroll
        for (int rr = 0; rr < 4; rr++) {
            int j = 2 * q + (rr & 1) + (rr >> 1) * 8;
            if (j < 9) {
                int jy = j / 3, jx = j - 3 * jy;
                const float* irow = imgb + (ry + jy) * 36;
                float f0 = c[t][rr >> 1][rr & 1] + bjv[rr];
                float f1 = c[t][rr >> 1][(rr & 1) + 2] + bjv[rr];
                o0 += f0 * irow[pxb + jx];
                o1 += f1 * irow[pxb + 8 + jx];
            }
        }
        o0 += __shfl_xor_sync(0xffffffffu, o0, 1);
        o0 += __shfl_xor_sync(0xffffffffu, o0, 2);
        o1 += __shfl_xor_sync(0xffffffffu, o1, 1);
        o1 += __shfl_xor_sync(0xffffffffu, o1, 2);
        if (q == 0) {
            float* orow = out + ((size_t)b * HH + y0 + ry) * WW + x0;
            orow[pxb] = o0;
            orow[pxb + 8] = o1;
        }
    }
}

extern "C" void kernel_launch(void* const* d_in, const int* in_sizes, int n_in,
                              void* d_out, int out_size) {
    const float* image = (const float*)d_in[0];
    const float* refer = (const float*)d_in[1];
    const float* w1    = (const float*)d_in[2];
    const float* b1    = (const float*)d_in[3];
    const float* w2    = (const float*)d_in[4];
    const float* b2    = (const float*)d_in[5];
    float* out = (float*)d_out;

    cudaFuncSetAttribute(conv2_mma_kernel,
                         cudaFuncAttributeMaxDynamicSharedMemorySize, SMEM_TOTAL);

    dim3 grid1(WW / 32, HH / 32, BATCH);
    conv1_kernel<<<grid1, 256>>>(image, refer, w1, b1);

    dim3 grid2(WW / 32, HH / 16, BATCH);
    conv2_mma_kernel<<<grid2, 256, SMEM_TOTAL>>>(w2, b2, image, out);
}

// round 9
// speedup vs baseline: 1.4223x; 1.0250x over previous
#include <cuda_runtime.h>
#include <cuda_bf16.h>
#include <cstdint>

#define BATCH 8
#define HH 512
#define WW 512

// h stored as bf16 hi/lo, grouped 8 channels per 16B:
// g_hb[((b*8+g)*512 + y)*512 + x] : uint4 = 8 bf16 (g<4: hi oc 8g..8g+7, g>=4: lo)
__device__ uint4 g_hb[(size_t)BATCH * 8 * HH * WW];
// Pre-packed B fragments: [tap][bsel][lane] -> uint4 (n16 fragment for one k16 chunk)
__device__ uint4 g_Bfrag[25 * 4 * 32];

typedef unsigned long long u64;
typedef unsigned short u16;
typedef unsigned int u32;

__device__ __forceinline__ u64 pk2(float lo, float hi) {
    u64 r; asm("mov.b64 %0, {%1, %2};" : "=l"(r) : "f"(lo), "f"(hi)); return r;
}
__device__ __forceinline__ void upk2(u64 p, float& lo, float& hi) {
    asm("mov.b64 {%0, %1}, %2;" : "=f"(lo), "=f"(hi) : "l"(p));
}
#define FMA2(acc, w, v) asm("fma.rn.f32x2 %0, %1, %2, %0;" : "+l"(acc) : "l"(w), "l"(v))

__device__ __forceinline__ u32 smem_u32(const void* p) {
    u32 a;
    asm("{ .reg .u64 t; cvta.to.shared.u64 t, %1; cvt.u32.u64 %0, t; }" : "=r"(a) : "l"(p));
    return a;
}

// ---------------------------------------------------------------------------
// Kernel 0: pack w2 into mma B fragments (hi/lo split).
// bsel 0: whi ch0-15, 1: whi ch16-31, 2: wlo ch0-15, 3: wlo ch16-31
// ---------------------------------------------------------------------------
__global__ void packB_kernel(const float* __restrict__ w2) {
    int i = blockIdx.x * 256 + threadIdx.x;
    if (i >= 25 * 4 * 32) return;
    int t = i & 31, bs = (i >> 5) & 3, tap = i >> 7;
    int tq = t & 3, tg = t >> 2;
    u32 regs[4];
    #pragma unroll
    for (int rr = 0; rr < 4; rr++) {
        int n = tg + (rr >> 1) * 8;
        int k0 = 2 * tq + (rr & 1) * 8;
        u16 v0 = 0, v1 = 0;
        if (n < 9) {
            int ch0 = (bs & 1) * 16 + k0;
            float w0 = w2[(n * 32 + ch0) * 25 + tap];
            float w1 = w2[(n * 32 + ch0 + 1) * 25 + tap];
            __nv_bfloat16 h0 = __float2bfloat16(w0);
            __nv_bfloat16 h1 = __float2bfloat16(w1);
            if (bs < 2) {
                v0 = __bfloat16_as_ushort(h0);
                v1 = __bfloat16_as_ushort(h1);
            } else {
                v0 = __bfloat16_as_ushort(__float2bfloat16(w0 - __bfloat162float(h0)));
                v1 = __bfloat16_as_ushort(__float2bfloat16(w1 - __bfloat162float(h1)));
            }
        }
        regs[rr] = (u32)v0 | ((u32)v1 << 16);
    }
    g_Bfrag[i] = make_uint4(regs[0], regs[1], regs[2], regs[3]);
}

// ---------------------------------------------------------------------------
// Kernel 1: conv5x5 (2->32) + bias + LeakyReLU -> bf16 hi/lo split, grouped.
// ---------------------------------------------------------------------------
__global__ __launch_bounds__(256, 2) void conv1_kernel(
    const float* __restrict__ img, const float* __restrict__ ref,
    const float* __restrict__ w1, const float* __restrict__ b1)
{
    __shared__ __align__(16) float sIn[2][36 * 40];
    __shared__ __align__(16) u64 sW[800];

    const int tid = threadIdx.x;
    const int bx = blockIdx.x, by = blockIdx.y, b = blockIdx.z;
    const int gx0 = bx * 32 - 2, gy0 = by * 32 - 2;

    const float* ib = img + (size_t)b * HH * WW;
    const float* rb = ref + (size_t)b * HH * WW;

    for (int i = tid; i < 36 * 40; i += 256) {
        int yy = i / 40, xx = i - yy * 40;
        int gy = gy0 + yy, gx = gx0 + xx;
        bool ok = ((unsigned)gy < HH) && ((unsigned)gx < WW) && (xx < 36);
        sIn[0][i] = ok ? ib[gy * WW + gx] : 0.f;
        sIn[1][i] = ok ? rb[gy * WW + gx] : 0.f;
    }
    for (int i = tid; i < 800; i += 256) {
        int p = i & 3, t = i >> 2;
        int k = t % 25, cw = t / 25;
        int q = cw >> 1, ci = cw & 1;
        int oc = q * 8 + 2 * p;
        float wlo = w1[(oc * 2 + ci) * 25 + k];
        float whi = w1[((oc + 1) * 2 + ci) * 25 + k];
        sW[i] = pk2(wlo, whi);
    }
    __syncthreads();

    const int lx0 = (tid & 7) * 4, ly = tid >> 3;
    const int ox = bx * 32 + lx0, oy = by * 32 + ly;

    #pragma unroll 1
    for (int q = 0; q < 4; q++) {
        u64 acc[4][4];
        #pragma unroll
        for (int p = 0; p < 4; p++)
            #pragma unroll
            for (int r = 0; r < 4; r++) acc[p][r] = 0ull;

        #pragma unroll 1
        for (int ci = 0; ci < 2; ci++) {
            const u64* wbase = &sW[(q * 2 + ci) * 100];
            const float* hbase = &sIn[ci][ly * 40 + lx0];
            #pragma unroll
            for (int dy = 0; dy < 5; dy++) {
                const float* rp = hbase + dy * 40;
                float4 a0 = *(const float4*)rp;
                float4 a1 = *(const float4*)(rp + 4);
                u64 D[8];
                D[0] = pk2(a0.x, a0.x); D[1] = pk2(a0.y, a0.y);
                D[2] = pk2(a0.z, a0.z); D[3] = pk2(a0.w, a0.w);
                D[4] = pk2(a1.x, a1.x); D[5] = pk2(a1.y, a1.y);
                D[6] = pk2(a1.z, a1.z); D[7] = pk2(a1.w, a1.w);
                #pragma unroll
                for (int dx = 0; dx < 5; dx++) {
                    const ulonglong2* wp =
                        (const ulonglong2*)(wbase + (dy * 5 + dx) * 4);
                    ulonglong2 wA = wp[0], wB = wp[1];
                    #pragma unroll
                    for (int r = 0; r < 4; r++) {
                        u64 v = D[dx + r];
                        FMA2(acc[0][r], wA.x, v);
                        FMA2(acc[1][r], wA.y, v);
                        FMA2(acc[2][r], wB.x, v);
                        FMA2(acc[3][r], wB.y, v);
                    }
                }
            }
        }

        float bs[8];
        #pragma unroll
        for (int o = 0; o < 8; o++) bs[o] = __ldg(&b1[q * 8 + o]);

        #pragma unroll
        for (int r = 0; r < 4; r++) {
            float v[8];
            #pragma unroll
            for (int p = 0; p < 4; p++) upk2(acc[p][r], v[2 * p], v[2 * p + 1]);
            u32 hw[4], lw[4];
            #pragma unroll
            for (int p = 0; p < 4; p++) {
                float a0 = v[2 * p] + bs[2 * p];
                float a1 = v[2 * p + 1] + bs[2 * p + 1];
                a0 = a0 >= 0.f ? a0 : 0.1f * a0;
                a1 = a1 >= 0.f ? a1 : 0.1f * a1;
                __nv_bfloat16 h0 = __float2bfloat16(a0);
                __nv_bfloat16 h1 = __float2bfloat16(a1);
                __nv_bfloat16 l0 = __float2bfloat16(a0 - __bfloat162float(h0));
                __nv_bfloat16 l1 = __float2bfloat16(a1 - __bfloat162float(h1));
                hw[p] = (u32)__bfloat16_as_ushort(h0) |
                        ((u32)__bfloat16_as_ushort(h1) << 16);
                lw[p] = (u32)__bfloat16_as_ushort(l0) |
                        ((u32)__bfloat16_as_ushort(l1) << 16);
            }
            size_t pix = (size_t)oy * WW + ox + r;
            g_hb[((size_t)(b * 8 + q) * HH * WW) + pix] =
                make_uint4(hw[0], hw[1], hw[2], hw[3]);
            g_hb[((size_t)(b * 8 + 4 + q) * HH * WW) + pix] =
                make_uint4(lw[0], lw[1], lw[2], lw[3]);
        }
    }
}

// ---------------------------------------------------------------------------
// Kernel 2: mma.sync bf16 implicit-GEMM conv2 + fused dynamic-filter apply.
// 512 threads (16 warps). CTA: 32 px x 16 rows. Warp: 1 row x 2 x-halves.
// B fragments from global (L1-resident). 2 CTAs/SM.
// ---------------------------------------------------------------------------
#define A_PITCH 144
#define NPIX (20 * 36)                    // h halo: 20 rows x 36 px
#define A_OFF 0
#define A_BYTES (NPIX * A_PITCH)          // 103,680
#define IMG_OFF A_BYTES
#define SMEM_TOTAL (IMG_OFF + 18 * 36 * 4)   // 106,272

__device__ __forceinline__ void ldmatrix4(u32& a0, u32& a1, u32& a2, u32& a3, u32 addr) {
    asm volatile("ldmatrix.sync.aligned.m8n8.x4.shared.b16 {%0,%1,%2,%3}, [%4];"
                 : "=r"(a0), "=r"(a1), "=r"(a2), "=r"(a3) : "r"(addr));
}
__device__ __forceinline__ void mma16816(float* c, const u32* a, u32 b0, u32 b1) {
    asm volatile(
        "mma.sync.aligned.m16n8k16.row.col.f32.bf16.bf16.f32 "
        "{%0,%1,%2,%3}, {%4,%5,%6,%7}, {%8,%9}, {%0,%1,%2,%3};"
        : "+f"(c[0]), "+f"(c[1]), "+f"(c[2]), "+f"(c[3])
        : "r"(a[0]), "r"(a[1]), "r"(a[2]), "r"(a[3]), "r"(b0), "r"(b1));
}

__global__ __launch_bounds__(512, 2) void conv2_mma_kernel(
    const float* __restrict__ b2,
    const float* __restrict__ img, float* __restrict__ out)
{
    extern __shared__ __align__(16) char smem[];
    const u32 sbase = smem_u32(smem);
    const int tid = threadIdx.x;
    const int wid = tid >> 5, lane = tid & 31;
    const int x0 = blockIdx.x * 32;
    const int y0 = blockIdx.y * 16;
    const int b = blockIdx.z;

    const int q = lane & 3, g = lane >> 2;
    float bjv[4];
    #pragma unroll
    for (int rr = 0; rr < 4; rr++) {
        int j = 2 * q + (rr & 1) + (rr >> 1) * 8;
        bjv[rr] = (j < 9) ? __ldg(&b2[j]) : 0.f;
    }

    const float* ib = img + (size_t)b * HH * WW;

    // ---- fill A halo: h rows y0-2 .. y0+17, px x0-2 .. x0+33 ----
    for (int i = tid; i < NPIX * 8; i += 512) {
        int gg = i / NPIX, pix = i - gg * NPIX;
        int yy = pix / 36, xx = pix - yy * 36;
        int gy = y0 - 2 + yy, gx = x0 - 2 + xx;
        uint4 v = make_uint4(0, 0, 0, 0);
        if (((unsigned)gy < HH) && ((unsigned)gx < WW))
            v = g_hb[((size_t)(b * 8 + gg) * HH + gy) * WW + gx];
        *(uint4*)(smem + A_OFF + pix * A_PITCH + gg * 16) = v;
    }
    // ---- fill img tile: rows y0-1 .. y0+16, px x0-1 .. x0+34 ----
    for (int i = tid; i < 18 * 36; i += 512) {
        int yy = i / 36, xx = i - yy * 36;
        int gy = y0 - 1 + yy, gx = x0 - 1 + xx;
        ((float*)(smem + IMG_OFF))[i] =
            (((unsigned)gy < HH) && ((unsigned)gx < WW)) ? ib[gy * WW + gx] : 0.f;
    }
    __syncthreads();

    // per-tile ldmatrix lane addresses: warp owns row wid, x-halves 0/1
    u32 tAddr[2];
    #pragma unroll
    for (int t = 0; t < 2; t++) {
        int pix = wid * 36 + t * 16 + (lane & 15);
        tAddr[t] = sbase + A_OFF + (u32)(pix * A_PITCH) + (u32)((lane >> 4) * 16);
    }

    float c[2][2][4];
    #pragma unroll
    for (int t = 0; t < 2; t++)
        #pragma unroll
        for (int n = 0; n < 2; n++)
            #pragma unroll
            for (int r = 0; r < 4; r++) c[t][n][r] = 0.f;

    #pragma unroll 1
    for (int dy = 0; dy < 5; dy++) {
        u32 dyOff = (u32)(dy * 36 * A_PITCH);
        #pragma unroll
        for (int dx = 0; dx < 5; dx++) {
            u32 tapOff = dyOff + (u32)(dx * A_PITCH);
            int tap = dy * 5 + dx;
            const uint4* bp = &g_Bfrag[tap * 128 + lane];
            uint4 bw0 = __ldg(bp);          // whi ch0-15
            uint4 bw1 = __ldg(bp + 32);     // whi ch16-31
            uint4 bl0 = __ldg(bp + 64);     // wlo ch0-15
            uint4 bl1 = __ldg(bp + 96);     // wlo ch16-31
            #pragma unroll
            for (int t = 0; t < 2; t++) {
                u32 base = tAddr[t] + tapOff;
                u32 a[4];
                // k0-15: hi ch0-15  -> whi0 (main) + wlo0 (cross)
                ldmatrix4(a[0], a[1], a[2], a[3], base);
                mma16816(c[t][0], a, bw0.x, bw0.y);
                mma16816(c[t][1], a, bw0.z, bw0.w);
                mma16816(c[t][0], a, bl0.x, bl0.y);
                mma16816(c[t][1], a, bl0.z, bl0.w);
                // k16-31: hi ch16-31 -> whi1 + wlo1
                ldmatrix4(a[0], a[1], a[2], a[3], base + 32);
                mma16816(c[t][0], a, bw1.x, bw1.y);
                mma16816(c[t][1], a, bw1.z, bw1.w);
                mma16816(c[t][0], a, bl1.x, bl1.y);
                mma16816(c[t][1], a, bl1.z, bl1.w);
                // k32-47: lo ch0-15 -> whi0
                ldmatrix4(a[0], a[1], a[2], a[3], base + 64);
                mma16816(c[t][0], a, bw0.x, bw0.y);
                mma16816(c[t][1], a, bw0.z, bw0.w);
                // k48-63: lo ch16-31 -> whi1
                ldmatrix4(a[0], a[1], a[2], a[3], base + 96);
                mma16816(c[t][0], a, bw1.x, bw1.y);
                mma16816(c[t][1], a, bw1.z, bw1.w);
            }
        }
    }

    // ---- epilogue: bias + dynamic 3x3 apply + quad reduce + store ----
    const float* imgb = (const float*)(smem + IMG_OFF);
    #pragma unroll
    for (int t = 0; t < 2; t++) {
        int pxb = t * 16 + g;
        float o0 = 0.f, o1 = 0.f;
        #pragma unroll
        for (int rr = 0; rr < 4; rr++) {
            int j = 2 * q + (rr & 1) + (rr >> 1) * 8;
            if (j < 9) {
                int jy = j / 3, jx = j - 3 * jy;
                const float* irow = imgb + (wid + jy) * 36;
                float f0 = c[t][rr >> 1][rr & 1] + bjv[rr];
                float f1 = c[t][rr >> 1][(rr & 1) + 2] + bjv[rr];
                o0 += f0 * irow[pxb + jx];
                o1 += f1 * irow[pxb + 8 + jx];
            }
        }
        o0 += __shfl_xor_sync(0xffffffffu, o0, 1);
        o0 += __shfl_xor_sync(0xffffffffu, o0, 2);
        o1 += __shfl_xor_sync(0xffffffffu, o1, 1);
        o1 += __shfl_xor_sync(0xffffffffu, o1, 2);
        if (q == 0) {
            float* orow = out + ((size_t)b * HH + y0 + wid) * WW + x0;
            orow[pxb] = o0;
            orow[pxb + 8] = o1;
        }
    }
}

extern "C" void kernel_launch(void* const* d_in, const int* in_sizes, int n_in,
                              void* d_out, int out_size) {
    const float* image = (const float*)d_in[0];
    const float* refer = (const float*)d_in[1];
    const float* w1    = (const float*)d_in[2];
    const float* b1    = (const float*)d_in[3];
    const float* w2    = (const float*)d_in[4];
    const float* b2    = (const float*)d_in[5];
    float* out = (float*)d_out;

    cudaFuncSetAttribute(conv2_mma_kernel,
                         cudaFuncAttributeMaxDynamicSharedMemorySize, SMEM_TOTAL);

    packB_kernel<<<13, 256>>>(w2);

    dim3 grid1(WW / 32, HH / 32, BATCH);
    conv1_kernel<<<grid1, 256>>>(image, refer, w1, b1);

    dim3 grid2(WW / 32, HH / 16, BATCH);
    conv2_mma_kernel<<<grid2, 512, SMEM_TOTAL>>>(b2, image, out);
}

// round 12
// speedup vs baseline: 2.0629x; 1.4504x over previous
#include <cuda_runtime.h>
#include <cuda_bf16.h>
#include <cstdint>

#define BATCH 8
#define HH 512
#define WW 512

// h stored as bf16 hi/lo, grouped 8 channels per 16B:
// g_hb[((b*8+g)*512 + y)*512 + x] : uint4 = 8 bf16 (g<4: hi oc 8g..8g+7, g>=4: lo)
__device__ uint4 g_hb[(size_t)BATCH * 8 * HH * WW];
// Pre-packed B fragments: [tap][bsel][lane] -> uint4
__device__ uint4 g_Bfrag[25 * 4 * 32];

typedef unsigned long long u64;
typedef unsigned short u16;
typedef unsigned int u32;

__device__ __forceinline__ u64 pk2(float lo, float hi) {
    u64 r; asm("mov.b64 %0, {%1, %2};" : "=l"(r) : "f"(lo), "f"(hi)); return r;
}
__device__ __forceinline__ void upk2(u64 p, float& lo, float& hi) {
    asm("mov.b64 {%0, %1}, %2;" : "=f"(lo), "=f"(hi) : "l"(p));
}
#define FMA2(acc, w, v) asm("fma.rn.f32x2 %0, %1, %2, %0;" : "+l"(acc) : "l"(w), "l"(v))

__device__ __forceinline__ u32 smem_u32(const void* p) {
    u32 a;
    asm("{ .reg .u64 t; cvta.to.shared.u64 t, %1; cvt.u32.u64 %0, t; }" : "=r"(a) : "l"(p));
    return a;
}

// ---------------------------------------------------------------------------
// Kernel 0: pack w2 into mma B fragments (hi/lo split).
// ---------------------------------------------------------------------------
__global__ void packB_kernel(const float* __restrict__ w2) {
    int i = blockIdx.x * 256 + threadIdx.x;
    if (i >= 25 * 4 * 32) return;
    int t = i & 31, bs = (i >> 5) & 3, tap = i >> 7;
    int tq = t & 3, tg = t >> 2;
    u32 regs[4];
    #pragma unroll
    for (int rr = 0; rr < 4; rr++) {
        int n = tg + (rr >> 1) * 8;
        int k0 = 2 * tq + (rr & 1) * 8;
        u16 v0 = 0, v1 = 0;
        if (n < 9) {
            int ch0 = (bs & 1) * 16 + k0;
            float w0 = w2[(n * 32 + ch0) * 25 + tap];
            float w1 = w2[(n * 32 + ch0 + 1) * 25 + tap];
            __nv_bfloat16 h0 = __float2bfloat16(w0);
            __nv_bfloat16 h1 = __float2bfloat16(w1);
            if (bs < 2) {
                v0 = __bfloat16_as_ushort(h0);
                v1 = __bfloat16_as_ushort(h1);
            } else {
                v0 = __bfloat16_as_ushort(__float2bfloat16(w0 - __bfloat162float(h0)));
                v1 = __bfloat16_as_ushort(__float2bfloat16(w1 - __bfloat162float(h1)));
            }
        }
        regs[rr] = (u32)v0 | ((u32)v1 << 16);
    }
    g_Bfrag[i] = make_uint4(regs[0], regs[1], regs[2], regs[3]);
}

// ---------------------------------------------------------------------------
// Kernel 1: conv5x5 (2->32) + bias + LeakyReLU -> bf16 hi/lo split, grouped.
// ---------------------------------------------------------------------------
__global__ __launch_bounds__(256, 2) void conv1_kernel(
    const float* __restrict__ img, const float* __restrict__ ref,
    const float* __restrict__ w1, const float* __restrict__ b1)
{
    __shared__ __align__(16) float sIn[2][36 * 40];
    __shared__ __align__(16) u64 sW[800];

    const int tid = threadIdx.x;
    const int bx = blockIdx.x, by = blockIdx.y, b = blockIdx.z;
    const int gx0 = bx * 32 - 2, gy0 = by * 32 - 2;

    const float* ib = img + (size_t)b * HH * WW;
    const float* rb = ref + (size_t)b * HH * WW;

    for (int i = tid; i < 36 * 40; i += 256) {
        int yy = i / 40, xx = i - yy * 40;
        int gy = gy0 + yy, gx = gx0 + xx;
        bool ok = ((unsigned)gy < HH) && ((unsigned)gx < WW) && (xx < 36);
        sIn[0][i] = ok ? ib[gy * WW + gx] : 0.f;
        sIn[1][i] = ok ? rb[gy * WW + gx] : 0.f;
    }
    for (int i = tid; i < 800; i += 256) {
        int p = i & 3, t = i >> 2;
        int k = t % 25, cw = t / 25;
        int q = cw >> 1, ci = cw & 1;
        int oc = q * 8 + 2 * p;
        float wlo = w1[(oc * 2 + ci) * 25 + k];
        float whi = w1[((oc + 1) * 2 + ci) * 25 + k];
        sW[i] = pk2(wlo, whi);
    }
    __syncthreads();

    const int lx0 = (tid & 7) * 4, ly = tid >> 3;
    const int ox = bx * 32 + lx0, oy = by * 32 + ly;

    #pragma unroll 1
    for (int q = 0; q < 4; q++) {
        u64 acc[4][4];
        #pragma unroll
        for (int p = 0; p < 4; p++)
            #pragma unroll
            for (int r = 0; r < 4; r++) acc[p][r] = 0ull;

        #pragma unroll 1
        for (int ci = 0; ci < 2; ci++) {
            const u64* wbase = &sW[(q * 2 + ci) * 100];
            const float* hbase = &sIn[ci][ly * 40 + lx0];
            #pragma unroll
            for (int dy = 0; dy < 5; dy++) {
                const float* rp = hbase + dy * 40;
                float4 a0 = *(const float4*)rp;
                float4 a1 = *(const float4*)(rp + 4);
                u64 D[8];
                D[0] = pk2(a0.x, a0.x); D[1] = pk2(a0.y, a0.y);
                D[2] = pk2(a0.z, a0.z); D[3] = pk2(a0.w, a0.w);
                D[4] = pk2(a1.x, a1.x); D[5] = pk2(a1.y, a1.y);
                D[6] = pk2(a1.z, a1.z); D[7] = pk2(a1.w, a1.w);
                #pragma unroll
                for (int dx = 0; dx < 5; dx++) {
                    const ulonglong2* wp =
                        (const ulonglong2*)(wbase + (dy * 5 + dx) * 4);
                    ulonglong2 wA = wp[0], wB = wp[1];
                    #pragma unroll
                    for (int r = 0; r < 4; r++) {
                        u64 v = D[dx + r];
                        FMA2(acc[0][r], wA.x, v);
                        FMA2(acc[1][r], wA.y, v);
                        FMA2(acc[2][r], wB.x, v);
                        FMA2(acc[3][r], wB.y, v);
                    }
                }
            }
        }

        float bs[8];
        #pragma unroll
        for (int o = 0; o < 8; o++) bs[o] = __ldg(&b1[q * 8 + o]);

        #pragma unroll
        for (int r = 0; r < 4; r++) {
            float v[8];
            #pragma unroll
            for (int p = 0; p < 4; p++) upk2(acc[p][r], v[2 * p], v[2 * p + 1]);
            u32 hw[4], lw[4];
            #pragma unroll
            for (int p = 0; p < 4; p++) {
                float a0 = v[2 * p] + bs[2 * p];
                float a1 = v[2 * p + 1] + bs[2 * p + 1];
                a0 = a0 >= 0.f ? a0 : 0.1f * a0;
                a1 = a1 >= 0.f ? a1 : 0.1f * a1;
                __nv_bfloat16 h0 = __float2bfloat16(a0);
                __nv_bfloat16 h1 = __float2bfloat16(a1);
                __nv_bfloat16 l0 = __float2bfloat16(a0 - __bfloat162float(h0));
                __nv_bfloat16 l1 = __float2bfloat16(a1 - __bfloat162float(h1));
                hw[p] = (u32)__bfloat16_as_ushort(h0) |
                        ((u32)__bfloat16_as_ushort(h1) << 16);
                lw[p] = (u32)__bfloat16_as_ushort(l0) |
                        ((u32)__bfloat16_as_ushort(l1) << 16);
            }
            size_t pix = (size_t)oy * WW + ox + r;
            g_hb[((size_t)(b * 8 + q) * HH * WW) + pix] =
                make_uint4(hw[0], hw[1], hw[2], hw[3]);
            g_hb[((size_t)(b * 8 + 4 + q) * HH * WW) + pix] =
                make_uint4(lw[0], lw[1], lw[2], lw[3]);
        }
    }
}

// ---------------------------------------------------------------------------
// Kernel 2: mma.sync bf16 implicit-GEMM conv2 + fused dynamic-filter apply.
// 256 threads (8 warps). CTA: 32 px x 8 rows; halo 12x36. 3 CTAs/SM.
// Warp: 1 row x 2 x-halves.
// ---------------------------------------------------------------------------
#define A_PITCH 144
#define NPIX (12 * 36)                    // 432
#define A_OFF 0
#define A_BYTES (NPIX * A_PITCH)          // 62,208
#define IMG_OFF A_BYTES
#define SMEM_TOTAL (IMG_OFF + 10 * 36 * 4)   // 63,648

__device__ __forceinline__ void ldmatrix4(u32& a0, u32& a1, u32& a2, u32& a3, u32 addr) {
    asm volatile("ldmatrix.sync.aligned.m8n8.x4.shared.b16 {%0,%1,%2,%3}, [%4];"
                 : "=r"(a0), "=r"(a1), "=r"(a2), "=r"(a3) : "r"(addr));
}
__device__ __forceinline__ void mma16816(float* c, const u32* a, u32 b0, u32 b1) {
    asm volatile(
        "mma.sync.aligned.m16n8k16.row.col.f32.bf16.bf16.f32 "
        "{%0,%1,%2,%3}, {%4,%5,%6,%7}, {%8,%9}, {%0,%1,%2,%3};"
        : "+f"(c[0]), "+f"(c[1]), "+f"(c[2]), "+f"(c[3])
        : "r"(a[0]), "r"(a[1]), "r"(a[2]), "r"(a[3]), "r"(b0), "r"(b1));
}

__global__ __launch_bounds__(256, 3) void conv2_mma_kernel(
    const float* __restrict__ b2,
    const float* __restrict__ img, float* __restrict__ out)
{
    extern __shared__ __align__(16) char smem[];
    const u32 sbase = smem_u32(smem);
    const int tid = threadIdx.x;
    const int wid = tid >> 5, lane = tid & 31;
    const int x0 = blockIdx.x * 32;
    const int y0 = blockIdx.y * 8;
    const int b = blockIdx.z;

    const int q = lane & 3, g = lane >> 2;
    float bjv[4];
    #pragma unroll
    for (int rr = 0; rr < 4; rr++) {
        int j = 2 * q + (rr & 1) + (rr >> 1) * 8;
        bjv[rr] = (j < 9) ? __ldg(&b2[j]) : 0.f;
    }

    const float* ib = img + (size_t)b * HH * WW;

    // ---- fill A halo: h rows y0-2 .. y0+9, px x0-2 .. x0+33 ----
    for (int i = tid; i < NPIX * 8; i += 256) {
        int gg = i / NPIX, pix = i - gg * NPIX;
        int yy = pix / 36, xx = pix - yy * 36;
        int gy = y0 - 2 + yy, gx = x0 - 2 + xx;
        uint4 v = make_uint4(0, 0, 0, 0);
        if (((unsigned)gy < HH) && ((unsigned)gx < WW))
            v = g_hb[((size_t)(b * 8 + gg) * HH + gy) * WW + gx];
        *(uint4*)(smem + A_OFF + pix * A_PITCH + gg * 16) = v;
    }
    // ---- fill img tile: rows y0-1 .. y0+8, px x0-1 .. x0+34 ----
    for (int i = tid; i < 10 * 36; i += 256) {
        int yy = i / 36, xx = i - yy * 36;
        int gy = y0 - 1 + yy, gx = x0 - 1 + xx;
        ((float*)(smem + IMG_OFF))[i] =
            (((unsigned)gy < HH) && ((unsigned)gx < WW)) ? ib[gy * WW + gx] : 0.f;
    }
    __syncthreads();

    // per-tile ldmatrix lane addresses: warp owns output row wid, x-halves 0/1
    u32 tAddr[2];
    #pragma unroll
    for (int t = 0; t < 2; t++) {
        int pix = wid * 36 + t * 16 + (lane & 15);
        tAddr[t] = sbase + A_OFF + (u32)(pix * A_PITCH) + (u32)((lane >> 4) * 16);
    }

    float c[2][2][4];
    #pragma unroll
    for (int t = 0; t < 2; t++)
        #pragma unroll
        for (int n = 0; n < 2; n++)
            #pragma unroll
            for (int r = 0; r < 4; r++) c[t][n][r] = 0.f;

    #pragma unroll 1
    for (int dy = 0; dy < 5; dy++) {
        u32 dyOff = (u32)(dy * 36 * A_PITCH);
        #pragma unroll
        for (int dx = 0; dx < 5; dx++) {
            u32 tapOff = dyOff + (u32)(dx * A_PITCH);
            int tap = dy * 5 + dx;
            const uint4* bp = &g_Bfrag[tap * 128 + lane];
            uint4 bw0 = __ldg(bp);          // whi ch0-15
            uint4 bw1 = __ldg(bp + 32);     // whi ch16-31
            uint4 bl0 = __ldg(bp + 64);     // wlo ch0-15
            uint4 bl1 = __ldg(bp + 96);     // wlo ch16-31
            #pragma unroll
            for (int t = 0; t < 2; t++) {
                u32 base = tAddr[t] + tapOff;
                u32 a[4];
                // k0-15: hi ch0-15 -> whi0 + wlo0
                ldmatrix4(a[0], a[1], a[2], a[3], base);
                mma16816(c[t][0], a, bw0.x, bw0.y);
                mma16816(c[t][1], a, bw0.z, bw0.w);
                mma16816(c[t][0], a, bl0.x, bl0.y);
                mma16816(c[t][1], a, bl0.z, bl0.w);
                // k16-31: hi ch16-31 -> whi1 + wlo1
                ldmatrix4(a[0], a[1], a[2], a[3], base + 32);
                mma16816(c[t][0], a, bw1.x, bw1.y);
                mma16816(c[t][1], a, bw1.z, bw1.w);
                mma16816(c[t][0], a, bl1.x, bl1.y);
                mma16816(c[t][1], a, bl1.z, bl1.w);
                // k32-47: lo ch0-15 -> whi0
                ldmatrix4(a[0], a[1], a[2], a[3], base + 64);
                mma16816(c[t][0], a, bw0.x, bw0.y);
                mma16816(c[t][1], a, bw0.z, bw0.w);
                // k48-63: lo ch16-31 -> whi1
                ldmatrix4(a[0], a[1], a[2], a[3], base + 96);
                mma16816(c[t][0], a, bw1.x, bw1.y);
                mma16816(c[t][1], a, bw1.z, bw1.w);
            }
        }
    }

    // ---- epilogue: bias + dynamic 3x3 apply + quad reduce + store ----
    const float* imgb = (const float*)(smem + IMG_OFF);
    #pragma unroll
    for (int t = 0; t < 2; t++) {
        int pxb = t * 16 + g;
        float o0 = 0.f, o1 = 0.f;
        #pragma unroll
        for (int rr = 0; rr < 4; rr++) {
            int j = 2 * q + (rr & 1) + (rr >> 1) * 8;
            if (j < 9) {
                int jy = j / 3, jx = j - 3 * jy;
                const float* irow = imgb + (wid + jy) * 36;
                float f0 = c[t][rr >> 1][rr & 1] + bjv[rr];
                float f1 = c[t][rr >> 1][(rr & 1) + 2] + bjv[rr];
                o0 += f0 * irow[pxb + jx];
                o1 += f1 * irow[pxb + 8 + jx];
            }
        }
        o0 += __shfl_xor_sync(0xffffffffu, o0, 1);
        o0 += __shfl_xor_sync(0xffffffffu, o0, 2);
        o1 += __shfl_xor_sync(0xffffffffu, o1, 1);
        o1 += __shfl_xor_sync(0xffffffffu, o1, 2);
        if (q == 0) {
            float* orow = out + ((size_t)b * HH + y0 + wid) * WW + x0;
            orow[pxb] = o0;
            orow[pxb + 8] = o1;
        }
    }
}

extern "C" void kernel_launch(void* const* d_in, const int* in_sizes, int n_in,
                              void* d_out, int out_size) {
    const float* image = (const float*)d_in[0];
    const float* refer = (const float*)d_in[1];
    const float* w1    = (const float*)d_in[2];
    const float* b1    = (const float*)d_in[3];
    const float* w2    = (const float*)d_in[4];
    const float* b2    = (const float*)d_in[5];
    float* out = (float*)d_out;

    cudaFuncSetAttribute(conv2_mma_kernel,
                         cudaFuncAttributeMaxDynamicSharedMemorySize, SMEM_TOTAL);

    packB_kernel<<<13, 256>>>(w2);

    dim3 grid1(WW / 32, HH / 32, BATCH);
    conv1_kernel<<<grid1, 256>>>(image, refer, w1, b1);

    dim3 grid2(WW / 32, HH / 8, BATCH);
    conv2_mma_kernel<<<grid2, 256, SMEM_TOTAL>>>(b2, image, out);
}

// round 16
// speedup vs baseline: 3.3572x; 1.6274x over previous
#include <cuda_runtime.h>
#include <cuda_bf16.h>
#include <cuda_fp16.h>
#include <cstdint>

#define BATCH 8
#define HH 512
#define WW 512

// h stored as single fp16, grouped 8 channels per 16B:
// g_h16[((b*4+g)*512 + y)*512 + x] : uint4 = 8 fp16 (group g -> ch 8g..8g+7)
__device__ uint4 g_h16[(size_t)BATCH * 4 * HH * WW];
// Pre-packed fp16 B fragments: [tap][kchunk][lane] -> uint4 (n16 frag for one k16)
__device__ uint4 g_Bfrag[25 * 2 * 32];

typedef unsigned long long u64;
typedef unsigned short u16;
typedef unsigned int u32;

__device__ __forceinline__ u64 pk2(float lo, float hi) {
    u64 r; asm("mov.b64 %0, {%1, %2};" : "=l"(r) : "f"(lo), "f"(hi)); return r;
}
__device__ __forceinline__ void upk2(u64 p, float& lo, float& hi) {
    asm("mov.b64 {%0, %1}, %2;" : "=f"(lo), "=f"(hi) : "l"(p));
}
#define FMA2(acc, w, v) asm("fma.rn.f32x2 %0, %1, %2, %0;" : "+l"(acc) : "l"(w), "l"(v))

__device__ __forceinline__ u32 smem_u32(const void* p) {
    u32 a;
    asm("{ .reg .u64 t; cvta.to.shared.u64 t, %1; cvt.u32.u64 %0, t; }" : "=r"(a) : "l"(p));
    return a;
}

// ---------------------------------------------------------------------------
// Kernel 0: pack w2 into fp16 mma B fragments.
// ---------------------------------------------------------------------------
__global__ void packB_kernel(const float* __restrict__ w2) {
    int i = blockIdx.x * 256 + threadIdx.x;
    if (i >= 25 * 2 * 32) return;
    int t = i & 31, kc = (i >> 5) & 1, tap = i >> 6;
    int tq = t & 3, tg = t >> 2;
    u32 regs[4];
    #pragma unroll
    for (int rr = 0; rr < 4; rr++) {
        int n = tg + (rr >> 1) * 8;
        int k0 = 2 * tq + (rr & 1) * 8;
        u16 v0 = 0, v1 = 0;
        if (n < 9) {
            int ch0 = kc * 16 + k0;
            __half h0 = __float2half(w2[(n * 32 + ch0) * 25 + tap]);
            __half h1 = __float2half(w2[(n * 32 + ch0 + 1) * 25 + tap]);
            v0 = __half_as_ushort(h0);
            v1 = __half_as_ushort(h1);
        }
        regs[rr] = (u32)v0 | ((u32)v1 << 16);
    }
    g_Bfrag[i] = make_uint4(regs[0], regs[1], regs[2], regs[3]);
}

// ---------------------------------------------------------------------------
// Kernel 1: conv5x5 (2->32) + bias + LeakyReLU -> fp16, grouped.
// ---------------------------------------------------------------------------
__global__ __launch_bounds__(256, 2) void conv1_kernel(
    const float* __restrict__ img, const float* __restrict__ ref,
    const float* __restrict__ w1, const float* __restrict__ b1)
{
    __shared__ __align__(16) float sIn[2][36 * 40];
    __shared__ __align__(16) u64 sW[800];

    const int tid = threadIdx.x;
    const int bx = blockIdx.x, by = blockIdx.y, b = blockIdx.z;
    const int gx0 = bx * 32 - 2, gy0 = by * 32 - 2;

    const float* ib = img + (size_t)b * HH * WW;
    const float* rb = ref + (size_t)b * HH * WW;

    for (int i = tid; i < 36 * 40; i += 256) {
        int yy = i / 40, xx = i - yy * 40;
        int gy = gy0 + yy, gx = gx0 + xx;
        bool ok = ((unsigned)gy < HH) && ((unsigned)gx < WW) && (xx < 36);
        sIn[0][i] = ok ? ib[gy * WW + gx] : 0.f;
        sIn[1][i] = ok ? rb[gy * WW + gx] : 0.f;
    }
    for (int i = tid; i < 800; i += 256) {
        int p = i & 3, t = i >> 2;
        int k = t % 25, cw = t / 25;
        int q = cw >> 1, ci = cw & 1;
        int oc = q * 8 + 2 * p;
        float wlo = w1[(oc * 2 + ci) * 25 + k];
        float whi = w1[((oc + 1) * 2 + ci) * 25 + k];
        sW[i] = pk2(wlo, whi);
    }
    __syncthreads();

    const int lx0 = (tid & 7) * 4, ly = tid >> 3;
    const int ox = bx * 32 + lx0, oy = by * 32 + ly;

    #pragma unroll 1
    for (int q = 0; q < 4; q++) {
        u64 acc[4][4];
        #pragma unroll
        for (int p = 0; p < 4; p++)
            #pragma unroll
            for (int r = 0; r < 4; r++) acc[p][r] = 0ull;

        #pragma unroll 1
        for (int ci = 0; ci < 2; ci++) {
            const u64* wbase = &sW[(q * 2 + ci) * 100];
            const float* hbase = &sIn[ci][ly * 40 + lx0];
            #pragma unroll
            for (int dy = 0; dy < 5; dy++) {
                const float* rp = hbase + dy * 40;
                float4 a0 = *(const float4*)rp;
                float4 a1 = *(const float4*)(rp + 4);
                u64 D[8];
                D[0] = pk2(a0.x, a0.x); D[1] = pk2(a0.y, a0.y);
                D[2] = pk2(a0.z, a0.z); D[3] = pk2(a0.w, a0.w);
                D[4] = pk2(a1.x, a1.x); D[5] = pk2(a1.y, a1.y);
                D[6] = pk2(a1.z, a1.z); D[7] = pk2(a1.w, a1.w);
                #pragma unroll
                for (int dx = 0; dx < 5; dx++) {
                    const ulonglong2* wp =
                        (const ulonglong2*)(wbase + (dy * 5 + dx) * 4);
                    ulonglong2 wA = wp[0], wB = wp[1];
                    #pragma unroll
                    for (int r = 0; r < 4; r++) {
                        u64 v = D[dx + r];
                        FMA2(acc[0][r], wA.x, v);
                        FMA2(acc[1][r], wA.y, v);
                        FMA2(acc[2][r], wB.x, v);
                        FMA2(acc[3][r], wB.y, v);
                    }
                }
            }
        }

        float bs[8];
        #pragma unroll
        for (int o = 0; o < 8; o++) bs[o] = __ldg(&b1[q * 8 + o]);

        #pragma unroll
        for (int r = 0; r < 4; r++) {
            float v[8];
            #pragma unroll
            for (int p = 0; p < 4; p++) upk2(acc[p][r], v[2 * p], v[2 * p + 1]);
            u32 hw[4];
            #pragma unroll
            for (int p = 0; p < 4; p++) {
                float a0 = v[2 * p] + bs[2 * p];
                float a1 = v[2 * p + 1] + bs[2 * p + 1];
                a0 = a0 >= 0.f ? a0 : 0.1f * a0;
                a1 = a1 >= 0.f ? a1 : 0.1f * a1;
                __half2 hh = __floats2half2_rn(a0, a1);
                hw[p] = *(u32*)&hh;
            }
            size_t pix = (size_t)oy * WW + ox + r;
            g_h16[((size_t)(b * 4 + q) * HH * WW) + pix] =
                make_uint4(hw[0], hw[1], hw[2], hw[3]);
        }
    }
}

// ---------------------------------------------------------------------------
// Kernel 2: mma.sync fp16 implicit-GEMM conv2 + fused dynamic-filter apply.
// 256 threads (8 warps). CTA: 32 px x 8 rows; halo 12x36. 3 CTAs/SM.
// Warp: 1 row x 2 x-halves. Single-product fp16 (K=32 per tap).
// ---------------------------------------------------------------------------
#define A_PITCH 80                        // 64 B data + 16 B pad
#define NPIX (12 * 36)                    // 432
#define A_OFF 0
#define A_BYTES (NPIX * A_PITCH)          // 34,560
#define IMG_OFF A_BYTES
#define SMEM_TOTAL (IMG_OFF + 10 * 36 * 4)   // 36,000

__device__ __forceinline__ void ldmatrix4(u32& a0, u32& a1, u32& a2, u32& a3, u32 addr) {
    asm volatile("ldmatrix.sync.aligned.m8n8.x4.shared.b16 {%0,%1,%2,%3}, [%4];"
                 : "=r"(a0), "=r"(a1), "=r"(a2), "=r"(a3) : "r"(addr));
}
__device__ __forceinline__ void mma16816(float* c, const u32* a, u32 b0, u32 b1) {
    asm volatile(
        "mma.sync.aligned.m16n8k16.row.col.f32.f16.f16.f32 "
        "{%0,%1,%2,%3}, {%4,%5,%6,%7}, {%8,%9}, {%0,%1,%2,%3};"
        : "+f"(c[0]), "+f"(c[1]), "+f"(c[2]), "+f"(c[3])
        : "r"(a[0]), "r"(a[1]), "r"(a[2]), "r"(a[3]), "r"(b0), "r"(b1));
}

__global__ __launch_bounds__(256, 3) void conv2_mma_kernel(
    const float* __restrict__ b2,
    const float* __restrict__ img, float* __restrict__ out)
{
    extern __shared__ __align__(16) char smem[];
    const u32 sbase = smem_u32(smem);
    const int tid = threadIdx.x;
    const int wid = tid >> 5, lane = tid & 31;
    const int x0 = blockIdx.x * 32;
    const int y0 = blockIdx.y * 8;
    const int b = blockIdx.z;

    const int q = lane & 3, g = lane >> 2;
    float bjv[4];
    #pragma unroll
    for (int rr = 0; rr < 4; rr++) {
        int j = 2 * q + (rr & 1) + (rr >> 1) * 8;
        bjv[rr] = (j < 9) ? __ldg(&b2[j]) : 0.f;
    }

    const float* ib = img + (size_t)b * HH * WW;

    // ---- fill A halo: h rows y0-2 .. y0+9, px x0-2 .. x0+33 (fp16, 4 groups) ----
    for (int i = tid; i < NPIX * 4; i += 256) {
        int gg = i / NPIX, pix = i - gg * NPIX;
        int yy = pix / 36, xx = pix - yy * 36;
        int gy = y0 - 2 + yy, gx = x0 - 2 + xx;
        uint4 v = make_uint4(0, 0, 0, 0);
        if (((unsigned)gy < HH) && ((unsigned)gx < WW))
            v = g_h16[((size_t)(b * 4 + gg) * HH + gy) * WW + gx];
        *(uint4*)(smem + A_OFF + pix * A_PITCH + gg * 16) = v;
    }
    // ---- fill img tile: rows y0-1 .. y0+8, px x0-1 .. x0+34 ----
    for (int i = tid; i < 10 * 36; i += 256) {
        int yy = i / 36, xx = i - yy * 36;
        int gy = y0 - 1 + yy, gx = x0 - 1 + xx;
        ((float*)(smem + IMG_OFF))[i] =
            (((unsigned)gy < HH) && ((unsigned)gx < WW)) ? ib[gy * WW + gx] : 0.f;
    }
    __syncthreads();

    // per-tile ldmatrix lane addresses: warp owns output row wid, x-halves 0/1
    u32 tAddr[2];
    #pragma unroll
    for (int t = 0; t < 2; t++) {
        int pix = wid * 36 + t * 16 + (lane & 15);
        tAddr[t] = sbase + A_OFF + (u32)(pix * A_PITCH) + (u32)((lane >> 4) * 16);
    }

    float c[2][2][4];
    #pragma unroll
    for (int t = 0; t < 2; t++)
        #pragma unroll
        for (int n = 0; n < 2; n++)
            #pragma unroll
            for (int r = 0; r < 4; r++) c[t][n][r] = 0.f;

    #pragma unroll 1
    for (int dy = 0; dy < 5; dy++) {
        u32 dyOff = (u32)(dy * 36 * A_PITCH);
        #pragma unroll
        for (int dx = 0; dx < 5; dx++) {
            u32 tapOff = dyOff + (u32)(dx * A_PITCH);
            int tap = dy * 5 + dx;
            const uint4* bp = &g_Bfrag[tap * 64 + lane];
            uint4 b0 = __ldg(bp);          // kchunk 0: ch0-15
            uint4 b1 = __ldg(bp + 32);     // kchunk 1: ch16-31
            #pragma unroll
            for (int t = 0; t < 2; t++) {
                u32 base = tAddr[t] + tapOff;
                u32 a[4];
                // ch0-15
                ldmatrix4(a[0], a[1], a[2], a[3], base);
                mma16816(c[t][0], a, b0.x, b0.y);
                mma16816(c[t][1], a, b0.z, b0.w);
                // ch16-31
                ldmatrix4(a[0], a[1], a[2], a[3], base + 32);
                mma16816(c[t][0], a, b1.x, b1.y);
                mma16816(c[t][1], a, b1.z, b1.w);
            }
        }
    }

    // ---- epilogue: bias + dynamic 3x3 apply + quad reduce + store ----
    const float* imgb = (const float*)(smem + IMG_OFF);
    #pragma unroll
    for (int t = 0; t < 2; t++) {
        int pxb = t * 16 + g;
        float o0 = 0.f, o1 = 0.f;
        #pragma unroll
        for (int rr = 0; rr < 4; rr++) {
            int j = 2 * q + (rr & 1) + (rr >> 1) * 8;
            if (j < 9) {
                int jy = j / 3, jx = j - 3 * jy;
                const float* irow = imgb + (wid + jy) * 36;
                float f0 = c[t][rr >> 1][rr & 1] + bjv[rr];
                float f1 = c[t][rr >> 1][(rr & 1) + 2] + bjv[rr];
                o0 += f0 * irow[pxb + jx];
                o1 += f1 * irow[pxb + 8 + jx];
            }
        }
        o0 += __shfl_xor_sync(0xffffffffu, o0, 1);
        o0 += __shfl_xor_sync(0xffffffffu, o0, 2);
        o1 += __shfl_xor_sync(0xffffffffu, o1, 1);
        o1 += __shfl_xor_sync(0xffffffffu, o1, 2);
        if (q == 0) {
            float* orow = out + ((size_t)b * HH + y0 + wid) * WW + x0;
            orow[pxb] = o0;
            orow[pxb + 8] = o1;
        }
    }
}

extern "C" void kernel_launch(void* const* d_in, const int* in_sizes, int n_in,
                              void* d_out, int out_size) {
    const float* image = (const float*)d_in[0];
    const float* refer = (const float*)d_in[1];
    const float* w1    = (const float*)d_in[2];
    const float* b1    = (const float*)d_in[3];
    const float* w2    = (const float*)d_in[4];
    const float* b2    = (const float*)d_in[5];
    float* out = (float*)d_out;

    cudaFuncSetAttribute(conv2_mma_kernel,
                         cudaFuncAttributeMaxDynamicSharedMemorySize, SMEM_TOTAL);

    packB_kernel<<<7, 256>>>(w2);

    dim3 grid1(WW / 32, HH / 32, BATCH);
    conv1_kernel<<<grid1, 256>>>(image, refer, w1, b1);

    dim3 grid2(WW / 32, HH / 8, BATCH);
    conv2_mma_kernel<<<grid2, 256, SMEM_TOTAL>>>(b2, image, out);
}